// round 7
// baseline (speedup 1.0000x reference)
#include <cuda_runtime.h>
#include <cstdint>
#include <climits>

#define BDIM 512
constexpr int Bn = 16, Nn = 2000, Hh = 512, Ww = 512, MAXD = 10, TOPK_ = 5;
constexpr float CONF = 0.2f, IOUT = 0.4f;
constexpr int KMAX = 256;
constexpr int FPI = 16;                    // fill blocks per image
constexpr int FILLB = Bn * FPI;            // 256 fill blocks
constexpr unsigned FULL = 0xffffffffu;

// release/acquire counters, one per image (reset at end of each replay)
__device__ int g_fc[Bn];

__device__ __forceinline__ float iou_f(float ax1, float ay1, float ax2, float ay2,
                                       float bx1, float by1, float bx2, float by2) {
    float aA = fmaxf(ax2 - ax1, 0.f) * fmaxf(ay2 - ay1, 0.f);
    float aB = fmaxf(bx2 - bx1, 0.f) * fmaxf(by2 - by1, 0.f);
    float ix1 = fmaxf(ax1, bx1), iy1 = fmaxf(ay1, by1);
    float ix2 = fminf(ax2, bx2), iy2 = fminf(ay2, by2);
    float it = fmaxf(ix2 - ix1, 0.f) * fmaxf(iy2 - iy1, 0.f);
    return it / (aA + aB - it + 1e-9f);
}

extern __shared__ unsigned char dynsmem[];
// NMS-block layout:
//   sscore : float[2048]   @ 0       (8192 B)
//   ckey   : ULL[2048]     @ 8192    (16384 B)
//   skeys  : ULL[2048]     @ 24576   (16384 B)
//   skept  : float4[KMAX]  @ 40960   (4096 B)
// total 45056 B

__global__ __launch_bounds__(BDIM) void fused_kernel(const float* __restrict__ region,
                                                     const float* __restrict__ neg,
                                                     float* __restrict__ out,
                                                     float* __restrict__ out_tb,
                                                     float* __restrict__ out_k2) {
    const int t = threadIdx.x;

    // ---------------- fill blocks: stream 1.0f, then release-count ----------------
    if (blockIdx.x >= Bn) {
        const int fb = blockIdx.x - Bn;
        const int img = fb >> 4;            // FPI = 16
        const int sub = fb & 15;
        float4* o4 = (float4*)out + (size_t)img * (Hh * Ww / 4) + sub * (Hh * Ww / 4 / FPI);
        float4 one = make_float4(1.f, 1.f, 1.f, 1.f);
#pragma unroll
        for (int i = 0; i < 8; i++) o4[t + i * BDIM] = one;   // 4096 float4 per block
        __threadfence();
        __syncthreads();
        if (t == 0) atomicAdd(&g_fc[img], 1);
        return;
    }

    // ---------------- NMS blocks ----------------
    float* sscore = (float*)dynsmem;
    unsigned long long* ckey  = (unsigned long long*)(dynsmem + 8192);
    unsigned long long* skeys = (unsigned long long*)(dynsmem + 24576);
    float4* skept = (float4*)(dynsmem + 40960);

    __shared__ int hist[256];
    __shared__ float sneg[MAXD * 5];
    __shared__ float okx1[MAXD], oky1[MAXD], okx2[MAXD], oky2[MAXD], oksc[MAXD];
    __shared__ float sxb[MAXD][5];
    __shared__ int s_ib[MAXD][4];
    __shared__ int s_k[MAXD];
    __shared__ unsigned int sh_maxbits;
    __shared__ int sh_binthr, sh_cnt, sh_found, sh_exh;

    const int b = blockIdx.x;
    const int lane = t & 31;
    const float* rb = region + (size_t)b * Nn * 5;

    if (t < 256) hist[t] = 0;
    if (t == 0) sh_maxbits = 0u;
    __syncthreads();

    // ---- single pass: score stage + max + histogram ----
    unsigned int lm = 0u;
    for (int j = t; j < Nn; j += BDIM) {
        float sc = __ldg(rb + j * 5 + 4);            // scores > 0
        sscore[j] = sc;
        lm = max(lm, __float_as_uint(sc));
        int bin = min(max((int)(sc * 256.0f), 0), 255);
        atomicAdd(&hist[bin], 1);
    }
#pragma unroll
    for (int off = 16; off; off >>= 1)
        lm = max(lm, __shfl_xor_sync(FULL, lm, off));
    if (lane == 0) atomicMax(&sh_maxbits, lm);
    if (t < MAXD * 5) sneg[t] = neg[(size_t)b * MAXD * 5 + t];
    __syncthreads();

    const bool has_conf = __uint_as_float(sh_maxbits) > CONF;
    const float thresh = has_conf ? CONF : 0.0f;
    const int limit = has_conf ? MAXD : TOPK_;

    // ---- candidate selection with escalation fallback ----
    for (int TARGET = 48;; TARGET <<= 2) {
        if (t < 32) {
            int base = 255 - lane * 8;
            int s = 0;
#pragma unroll
            for (int i = 0; i < 8; i++) s += hist[base - i];
            int pre = s;
#pragma unroll
            for (int off = 1; off < 32; off <<= 1) {
                int v = __shfl_up_sync(FULL, pre, off);
                if (lane >= off) pre += v;
            }
            unsigned bal = __ballot_sync(FULL, pre >= TARGET);
            if (bal) {
                int lw = __ffs(bal) - 1;
                if (lane == lw) {
                    int run = pre - s;
                    int binthr = 0;
#pragma unroll
                    for (int i = 0; i < 8; i++) {
                        run += hist[base - i];
                        if (run >= TARGET) { binthr = base - i; break; }
                    }
                    sh_binthr = binthr;
                }
            } else if (lane == 0) {
                sh_binthr = 0;
            }
            if (lane == 0) { sh_exh = (bal == 0); sh_cnt = 0; sh_found = 0; }
        }
        __syncthreads();
        const int binthr = sh_binthr;

        for (int j = t; j < Nn; j += BDIM) {
            float sc = sscore[j];
            if (sc > thresh) {
                int bin = min(max((int)(sc * 256.0f), 0), 255);
                if (bin >= binthr) {
                    int pos = atomicAdd(&sh_cnt, 1);
                    if (pos < 2048)
                        ckey[pos] = ((unsigned long long)__float_as_uint(sc) << 32) |
                                    (unsigned)(Nn - 1 - j);
                }
            }
        }
        __syncthreads();
        const int C = min(sh_cnt, 2048);

        // rank sort (descending; keys unique -> exact stable order)
        for (int i = t; i < C; i += BDIM) {
            unsigned long long ki = ckey[i];
            int r = 0;
            for (int j = 0; j < C; j++) r += (ckey[j] > ki);
            skeys[r] = ki;
        }
        __syncthreads();

        // ---- single-warp greedy NMS: candidate per lane, suppressor-list check ----
        if (t < 32) {
            int nkept = 0, found = 0;
            for (int c0 = 0; c0 < C; c0 += 32) {
                int ci = c0 + lane;
                bool validl = ci < C;
                float x1 = 0.f, y1 = 0.f, x2 = 0.f, y2 = 0.f, sc = 0.f;
                if (validl) {
                    unsigned long long key = skeys[ci];
                    int js = (Nn - 1) - (int)(unsigned)(key & 0xffffffffu);
                    x1 = __ldg(rb + js * 5 + 0);
                    y1 = __ldg(rb + js * 5 + 1);
                    x2 = __ldg(rb + js * 5 + 2);
                    y2 = __ldg(rb + js * 5 + 3);
                    sc = __uint_as_float((unsigned)(key >> 32));
                }
                bool decided = !validl;
                for (int k = 0; k < nkept; k++) {
                    float4 kb = skept[k];
                    if (!decided && iou_f(kb.x, kb.y, kb.z, kb.w, x1, y1, x2, y2) > IOUT)
                        decided = true;
                }
                bool stop = false;
                for (;;) {
                    unsigned und = __ballot_sync(FULL, !decided);
                    if (!und) break;
                    int i0 = __ffs(und) - 1;
                    float ax1 = __shfl_sync(FULL, x1, i0);
                    float ay1 = __shfl_sync(FULL, y1, i0);
                    float ax2 = __shfl_sync(FULL, x2, i0);
                    float ay2 = __shfl_sync(FULL, y2, i0);
                    if (lane == i0) {
                        skept[nkept] = make_float4(x1, y1, x2, y2);
                        decided = true;
                    }
                    nkept++;
                    bool tiny_ok = (ax2 - ax1 >= 1.0f) && (ay2 - ay1 >= 1.0f);
                    if (tiny_ok) {
                        if (lane == i0) {
                            okx1[found] = x1; oky1[found] = y1;
                            okx2[found] = x2; oky2[found] = y2;
                            oksc[found] = sc;
                        }
                        found++;
                        if (found == limit) { stop = true; break; }
                    }
                    if (!decided &&
                        iou_f(ax1, ay1, ax2, ay2, x1, y1, x2, y2) > IOUT)
                        decided = true;
                    if (nkept == KMAX) { stop = true; break; }
                }
                __syncwarp();
                if (stop) break;
            }
            if (lane == 0) sh_found = found;
        }
        __syncthreads();

        if (sh_found >= limit || sh_exh || TARGET >= Nn) break;
    }

    // ---- stage 2: warp-parallel 10-box merge + stable sort + NMS + outputs ----
    if (t < 32) {
        const int cnt = min(sh_found, limit);
        float bx[5];
        bx[0] = bx[1] = bx[2] = bx[3] = 0.f;
        bx[4] = -1.0f;
        if (lane < MAXD) {
            if (lane < cnt) {
                bx[0] = okx1[lane]; bx[1] = oky1[lane];
                bx[2] = okx2[lane]; bx[3] = oky2[lane];
                bx[4] = oksc[lane];
            } else {
#pragma unroll
                for (int c = 0; c < 5; c++) bx[c] = sneg[lane * 5 + c];
            }
        }
        int rank = 0;
#pragma unroll
        for (int j = 0; j < MAXD; j++) {
            float cj = __shfl_sync(FULL, bx[4], j);
            rank += (cj > bx[4]) || (cj == bx[4] && j < lane);
        }
        if (lane < MAXD) {
#pragma unroll
            for (int c = 0; c < 5; c++) sxb[rank][c] = bx[c];
        }
        __syncwarp();
        if (lane < MAXD) {
#pragma unroll
            for (int c = 0; c < 5; c++) bx[c] = sxb[lane][c];
        }
        bool kp = (lane < MAXD) && (bx[4] > 0.0f);
#pragma unroll
        for (int i = 0; i < MAXD; i++) {
            float ax1 = __shfl_sync(FULL, bx[0], i);
            float ay1 = __shfl_sync(FULL, bx[1], i);
            float ax2 = __shfl_sync(FULL, bx[2], i);
            float ay2 = __shfl_sync(FULL, bx[3], i);
            int ki = __shfl_sync(FULL, (int)kp, i);
            if (ki && lane > i && kp) {
                if (iou_f(ax1, ay1, ax2, ay2, bx[0], bx[1], bx[2], bx[3]) > IOUT)
                    kp = false;
            }
        }
        if (lane < MAXD) {
#pragma unroll
            for (int c = 0; c < 4; c++) {
                out_tb[(size_t)b * MAXD * 4 + lane * 4 + c] = kp ? bx[c] : 0.0f;
                s_ib[lane][c] = (int)floorf(bx[c] + 0.5f);
            }
            out_k2[(size_t)b * MAXD + lane] = kp ? 1.0f : 0.0f;
            s_k[lane] = kp ? 1 : 0;
        }
    }
    __syncthreads();

    // ---- wait for this image's fill to be complete (acquire), then zero covered ----
    if (t == 0) {
        while (atomicAdd(&g_fc[b], 0) < FPI) { }
        __threadfence();
    }
    __syncthreads();

    float* base = out + (size_t)b * Hh * Ww;
#pragma unroll
    for (int k = 0; k < MAXD; k++) {
        if (!s_k[k]) continue;
        int x1 = max(s_ib[k][0], 0), y1 = max(s_ib[k][1], 0);
        int x2 = min(s_ib[k][2], Ww), y2 = min(s_ib[k][3], Hh);
        int w = x2 - x1, h = y2 - y1;
        if (w <= 0 || h <= 0) continue;
        int area = w * h;
        for (int i = t; i < area; i += BDIM) {
            int y = y1 + i / w, x = x1 + i % w;
            base[y * Ww + x] = 0.0f;
        }
    }
    __syncthreads();
    if (t == 0) g_fc[b] = 0;       // reset for next graph replay
}

extern "C" void kernel_launch(void* const* d_in, const int* in_sizes, int n_in,
                              void* d_out, int out_size) {
    // inputs: [0]=x (unused), [1]=region_boxes (B,N,5), [2]=neg_boxes (B,10,5)
    const float* region = (const float*)d_in[1];
    const float* neg = (const float*)d_in[2];
    float* out = (float*)d_out;
    float* out_tb = out + (size_t)Bn * Hh * Ww;          // target_boxes segment
    float* out_k2 = out_tb + (size_t)Bn * MAXD * 4;      // keep2 segment

    const int smem_bytes = 45056;
    cudaFuncSetAttribute(fused_kernel, cudaFuncAttributeMaxDynamicSharedMemorySize, smem_bytes);

    fused_kernel<<<Bn + FILLB, BDIM, smem_bytes>>>(region, neg, out, out_tb, out_k2);
}

// round 8
// speedup vs baseline: 1.1175x; 1.1175x over previous
#include <cuda_runtime.h>
#include <cstdint>
#include <climits>

#define BDIM 512
constexpr int Bn = 16, Nn = 2000, Hh = 512, Ww = 512, MAXD = 10, TOPK_ = 5;
constexpr float CONF = 0.2f, IOUT = 0.4f;
constexpr int KMAX = 256;
constexpr int FPI = 16;                    // fill blocks per image
constexpr int FILLB = Bn * FPI;            // 256 fill blocks
constexpr unsigned FULL = 0xffffffffu;

// release/acquire counters, one per image (reset at end of each replay)
__device__ int g_fc[Bn];

__device__ __forceinline__ float iou_f(float ax1, float ay1, float ax2, float ay2,
                                       float bx1, float by1, float bx2, float by2) {
    float aA = fmaxf(ax2 - ax1, 0.f) * fmaxf(ay2 - ay1, 0.f);
    float aB = fmaxf(bx2 - bx1, 0.f) * fmaxf(by2 - by1, 0.f);
    float ix1 = fmaxf(ax1, bx1), iy1 = fmaxf(ay1, by1);
    float ix2 = fminf(ax2, bx2), iy2 = fminf(ay2, by2);
    float it = fmaxf(ix2 - ix1, 0.f) * fmaxf(iy2 - iy1, 0.f);
    return it / (aA + aB - it + 1e-9f);
}

extern __shared__ unsigned char dynsmem[];
// NMS-block layout:
//   sscore : float[2048]   @ 0       (8192 B)
//   ckey   : ULL[2048]     @ 8192    (16384 B)
//   skeys  : ULL[2048]     @ 24576   (16384 B)
//   skept  : float4[KMAX]  @ 40960   (4096 B)
// total 45056 B

__global__ __launch_bounds__(BDIM) void fused_kernel(const float* __restrict__ region,
                                                     const float* __restrict__ neg,
                                                     float* __restrict__ out,
                                                     float* __restrict__ out_tb,
                                                     float* __restrict__ out_k2) {
    const int t = threadIdx.x;

    // ---------------- fill blocks: stream 1.0f, then release-count ----------------
    if (blockIdx.x >= Bn) {
        const int fb = blockIdx.x - Bn;
        const int img = fb >> 4;            // FPI = 16
        const int sub = fb & 15;
        float4* o4 = (float4*)out + (size_t)img * (Hh * Ww / 4) + sub * (Hh * Ww / 4 / FPI);
        float4 one = make_float4(1.f, 1.f, 1.f, 1.f);
#pragma unroll
        for (int i = 0; i < 8; i++) o4[t + i * BDIM] = one;   // 4096 float4 per block
        // ONE fence per block: bar.sync orders all threads' stores before t0's
        // cumulative membar, then the release increment publishes them.
        __syncthreads();
        if (t == 0) {
            __threadfence();
            atomicAdd(&g_fc[img], 1);
        }
        return;
    }

    // ---------------- NMS blocks ----------------
    float* sscore = (float*)dynsmem;
    unsigned long long* ckey  = (unsigned long long*)(dynsmem + 8192);
    unsigned long long* skeys = (unsigned long long*)(dynsmem + 24576);
    float4* skept = (float4*)(dynsmem + 40960);

    __shared__ int hist[256];
    __shared__ float sneg[MAXD * 5];
    __shared__ float okx1[MAXD], oky1[MAXD], okx2[MAXD], oky2[MAXD], oksc[MAXD];
    __shared__ float sxb[MAXD][5];
    __shared__ int s_ib[MAXD][4];
    __shared__ int s_k[MAXD];
    __shared__ unsigned int sh_maxbits;
    __shared__ int sh_binthr, sh_cnt, sh_found, sh_exh;

    const int b = blockIdx.x;
    const int lane = t & 31;
    const float* rb = region + (size_t)b * Nn * 5;

    if (t < 256) hist[t] = 0;
    if (t == 0) sh_maxbits = 0u;
    __syncthreads();

    // ---- single pass: score stage + max + histogram ----
    unsigned int lm = 0u;
    for (int j = t; j < Nn; j += BDIM) {
        float sc = __ldg(rb + j * 5 + 4);            // scores > 0
        sscore[j] = sc;
        lm = max(lm, __float_as_uint(sc));
        int bin = min(max((int)(sc * 256.0f), 0), 255);
        atomicAdd(&hist[bin], 1);
    }
#pragma unroll
    for (int off = 16; off; off >>= 1)
        lm = max(lm, __shfl_xor_sync(FULL, lm, off));
    if (lane == 0) atomicMax(&sh_maxbits, lm);
    if (t < MAXD * 5) sneg[t] = neg[(size_t)b * MAXD * 5 + t];
    __syncthreads();

    const bool has_conf = __uint_as_float(sh_maxbits) > CONF;
    const float thresh = has_conf ? CONF : 0.0f;
    const int limit = has_conf ? MAXD : TOPK_;

    // ---- candidate selection with escalation fallback ----
    for (int TARGET = 48;; TARGET <<= 2) {
        if (t < 32) {
            int base = 255 - lane * 8;
            int s = 0;
#pragma unroll
            for (int i = 0; i < 8; i++) s += hist[base - i];
            int pre = s;
#pragma unroll
            for (int off = 1; off < 32; off <<= 1) {
                int v = __shfl_up_sync(FULL, pre, off);
                if (lane >= off) pre += v;
            }
            unsigned bal = __ballot_sync(FULL, pre >= TARGET);
            if (bal) {
                int lw = __ffs(bal) - 1;
                if (lane == lw) {
                    int run = pre - s;
                    int binthr = 0;
#pragma unroll
                    for (int i = 0; i < 8; i++) {
                        run += hist[base - i];
                        if (run >= TARGET) { binthr = base - i; break; }
                    }
                    sh_binthr = binthr;
                }
            } else if (lane == 0) {
                sh_binthr = 0;
            }
            if (lane == 0) { sh_exh = (bal == 0); sh_cnt = 0; sh_found = 0; }
        }
        __syncthreads();
        const int binthr = sh_binthr;

        for (int j = t; j < Nn; j += BDIM) {
            float sc = sscore[j];
            if (sc > thresh) {
                int bin = min(max((int)(sc * 256.0f), 0), 255);
                if (bin >= binthr) {
                    int pos = atomicAdd(&sh_cnt, 1);
                    if (pos < 2048)
                        ckey[pos] = ((unsigned long long)__float_as_uint(sc) << 32) |
                                    (unsigned)(Nn - 1 - j);
                }
            }
        }
        __syncthreads();
        const int C = min(sh_cnt, 2048);

        // rank sort (descending; keys unique -> exact stable order)
        for (int i = t; i < C; i += BDIM) {
            unsigned long long ki = ckey[i];
            int r = 0;
            for (int j = 0; j < C; j++) r += (ckey[j] > ki);
            skeys[r] = ki;
        }
        __syncthreads();

        // ---- single-warp greedy NMS: candidate per lane, suppressor-list check ----
        if (t < 32) {
            int nkept = 0, found = 0;
            for (int c0 = 0; c0 < C; c0 += 32) {
                int ci = c0 + lane;
                bool validl = ci < C;
                float x1 = 0.f, y1 = 0.f, x2 = 0.f, y2 = 0.f, sc = 0.f;
                if (validl) {
                    unsigned long long key = skeys[ci];
                    int js = (Nn - 1) - (int)(unsigned)(key & 0xffffffffu);
                    x1 = __ldg(rb + js * 5 + 0);
                    y1 = __ldg(rb + js * 5 + 1);
                    x2 = __ldg(rb + js * 5 + 2);
                    y2 = __ldg(rb + js * 5 + 3);
                    sc = __uint_as_float((unsigned)(key >> 32));
                }
                bool decided = !validl;
                for (int k = 0; k < nkept; k++) {
                    float4 kb = skept[k];
                    if (!decided && iou_f(kb.x, kb.y, kb.z, kb.w, x1, y1, x2, y2) > IOUT)
                        decided = true;
                }
                bool stop = false;
                for (;;) {
                    unsigned und = __ballot_sync(FULL, !decided);
                    if (!und) break;
                    int i0 = __ffs(und) - 1;
                    float ax1 = __shfl_sync(FULL, x1, i0);
                    float ay1 = __shfl_sync(FULL, y1, i0);
                    float ax2 = __shfl_sync(FULL, x2, i0);
                    float ay2 = __shfl_sync(FULL, y2, i0);
                    if (lane == i0) {
                        skept[nkept] = make_float4(x1, y1, x2, y2);
                        decided = true;
                    }
                    nkept++;
                    bool tiny_ok = (ax2 - ax1 >= 1.0f) && (ay2 - ay1 >= 1.0f);
                    if (tiny_ok) {
                        if (lane == i0) {
                            okx1[found] = x1; oky1[found] = y1;
                            okx2[found] = x2; oky2[found] = y2;
                            oksc[found] = sc;
                        }
                        found++;
                        if (found == limit) { stop = true; break; }
                    }
                    if (!decided &&
                        iou_f(ax1, ay1, ax2, ay2, x1, y1, x2, y2) > IOUT)
                        decided = true;
                    if (nkept == KMAX) { stop = true; break; }
                }
                __syncwarp();
                if (stop) break;
            }
            if (lane == 0) sh_found = found;
        }
        __syncthreads();

        if (sh_found >= limit || sh_exh || TARGET >= Nn) break;
    }

    // ---- stage 2: warp-parallel 10-box merge + stable sort + NMS + outputs ----
    if (t < 32) {
        const int cnt = min(sh_found, limit);
        float bx[5];
        bx[0] = bx[1] = bx[2] = bx[3] = 0.f;
        bx[4] = -1.0f;
        if (lane < MAXD) {
            if (lane < cnt) {
                bx[0] = okx1[lane]; bx[1] = oky1[lane];
                bx[2] = okx2[lane]; bx[3] = oky2[lane];
                bx[4] = oksc[lane];
            } else {
#pragma unroll
                for (int c = 0; c < 5; c++) bx[c] = sneg[lane * 5 + c];
            }
        }
        int rank = 0;
#pragma unroll
        for (int j = 0; j < MAXD; j++) {
            float cj = __shfl_sync(FULL, bx[4], j);
            rank += (cj > bx[4]) || (cj == bx[4] && j < lane);
        }
        if (lane < MAXD) {
#pragma unroll
            for (int c = 0; c < 5; c++) sxb[rank][c] = bx[c];
        }
        __syncwarp();
        if (lane < MAXD) {
#pragma unroll
            for (int c = 0; c < 5; c++) bx[c] = sxb[lane][c];
        }
        bool kp = (lane < MAXD) && (bx[4] > 0.0f);
#pragma unroll
        for (int i = 0; i < MAXD; i++) {
            float ax1 = __shfl_sync(FULL, bx[0], i);
            float ay1 = __shfl_sync(FULL, bx[1], i);
            float ax2 = __shfl_sync(FULL, bx[2], i);
            float ay2 = __shfl_sync(FULL, bx[3], i);
            int ki = __shfl_sync(FULL, (int)kp, i);
            if (ki && lane > i && kp) {
                if (iou_f(ax1, ay1, ax2, ay2, bx[0], bx[1], bx[2], bx[3]) > IOUT)
                    kp = false;
            }
        }
        if (lane < MAXD) {
#pragma unroll
            for (int c = 0; c < 4; c++) {
                out_tb[(size_t)b * MAXD * 4 + lane * 4 + c] = kp ? bx[c] : 0.0f;
                s_ib[lane][c] = (int)floorf(bx[c] + 0.5f);
            }
            out_k2[(size_t)b * MAXD + lane] = kp ? 1.0f : 0.0f;
            s_k[lane] = kp ? 1 : 0;
        }
    }
    __syncthreads();

    // ---- wait for this image's fill to be complete (acquire), then zero covered ----
    if (t == 0) {
        while (atomicAdd(&g_fc[b], 0) < FPI) { }
        __threadfence();
    }
    __syncthreads();

    float* base = out + (size_t)b * Hh * Ww;
#pragma unroll
    for (int k = 0; k < MAXD; k++) {
        if (!s_k[k]) continue;
        int x1 = max(s_ib[k][0], 0), y1 = max(s_ib[k][1], 0);
        int x2 = min(s_ib[k][2], Ww), y2 = min(s_ib[k][3], Hh);
        int w = x2 - x1, h = y2 - y1;
        if (w <= 0 || h <= 0) continue;
        int area = w * h;
        for (int i = t; i < area; i += BDIM) {
            int y = y1 + i / w, x = x1 + i % w;
            base[y * Ww + x] = 0.0f;
        }
    }
    __syncthreads();
    if (t == 0) g_fc[b] = 0;       // reset for next graph replay
}

extern "C" void kernel_launch(void* const* d_in, const int* in_sizes, int n_in,
                              void* d_out, int out_size) {
    // inputs: [0]=x (unused), [1]=region_boxes (B,N,5), [2]=neg_boxes (B,10,5)
    const float* region = (const float*)d_in[1];
    const float* neg = (const float*)d_in[2];
    float* out = (float*)d_out;
    float* out_tb = out + (size_t)Bn * Hh * Ww;          // target_boxes segment
    float* out_k2 = out_tb + (size_t)Bn * MAXD * 4;      // keep2 segment

    const int smem_bytes = 45056;
    cudaFuncSetAttribute(fused_kernel, cudaFuncAttributeMaxDynamicSharedMemorySize, smem_bytes);

    fused_kernel<<<Bn + FILLB, BDIM, smem_bytes>>>(region, neg, out, out_tb, out_k2);
}

// round 9
// speedup vs baseline: 1.1196x; 1.0019x over previous
#include <cuda_runtime.h>
#include <cstdint>
#include <climits>

#define BDIM 512
constexpr int Bn = 16, Nn = 2000, Hh = 512, Ww = 512, MAXD = 10, TOPK_ = 5;
constexpr float CONF = 0.2f, IOUT = 0.4f;
constexpr int KMAX = 256;
constexpr int GRID = 148;                  // one wave: one block per SM
constexpr int FILLB = GRID - Bn;           // 132 fill blocks
constexpr unsigned FULL = 0xffffffffu;

// release/acquire counters (reset by last NMS block each replay)
__device__ int g_fc;
__device__ int g_done;

__device__ __forceinline__ float iou_f(float ax1, float ay1, float ax2, float ay2,
                                       float bx1, float by1, float bx2, float by2) {
    float aA = fmaxf(ax2 - ax1, 0.f) * fmaxf(ay2 - ay1, 0.f);
    float aB = fmaxf(bx2 - bx1, 0.f) * fmaxf(by2 - by1, 0.f);
    float ix1 = fmaxf(ax1, bx1), iy1 = fmaxf(ay1, by1);
    float ix2 = fminf(ax2, bx2), iy2 = fminf(ay2, by2);
    float it = fmaxf(ix2 - ix1, 0.f) * fmaxf(iy2 - iy1, 0.f);
    return it / (aA + aB - it + 1e-9f);
}

extern __shared__ unsigned char dynsmem[];
// NMS-block layout:
//   sscore : float[2048]   @ 0       (8192 B)
//   ckey   : ULL[2048]     @ 8192    (16384 B)
//   skeys  : ULL[2048]     @ 24576   (16384 B)
//   skept  : float4[KMAX]  @ 40960   (4096 B)
// total 45056 B

__global__ __launch_bounds__(BDIM) void fused_kernel(const float* __restrict__ region,
                                                     const float* __restrict__ neg,
                                                     float* __restrict__ out,
                                                     float* __restrict__ out_tb,
                                                     float* __restrict__ out_k2) {
    const int t = threadIdx.x;

    // ---------------- fill blocks: flat stream of 1.0f over whole mask ----------------
    if (blockIdx.x >= Bn) {
        const int fb = blockIdx.x - Bn;
        const int total4 = Bn * Hh * Ww / 4;                 // 1048576 float4
        const int per = (total4 + FILLB - 1) / FILLB;        // 7944
        float4* o4 = (float4*)out;
        float4 one = make_float4(1.f, 1.f, 1.f, 1.f);
        int base = fb * per;
        int end = min(base + per, total4);
        for (int i = base + t; i < end; i += BDIM) o4[i] = one;
        // one fence per block, then release
        __syncthreads();
        if (t == 0) {
            __threadfence();
            atomicAdd(&g_fc, 1);
        }
        return;
    }

    // ---------------- NMS blocks ----------------
    float* sscore = (float*)dynsmem;
    unsigned long long* ckey  = (unsigned long long*)(dynsmem + 8192);
    unsigned long long* skeys = (unsigned long long*)(dynsmem + 24576);
    float4* skept = (float4*)(dynsmem + 40960);

    __shared__ int hist[256];
    __shared__ float sneg[MAXD * 5];
    __shared__ float okx1[MAXD], oky1[MAXD], okx2[MAXD], oky2[MAXD], oksc[MAXD];
    __shared__ float sxb[MAXD][5];
    __shared__ int s_ib[MAXD][4];
    __shared__ int s_k[MAXD];
    __shared__ unsigned int sh_maxbits;
    __shared__ int sh_binthr, sh_cnt, sh_found, sh_exh;

    const int b = blockIdx.x;
    const int lane = t & 31;
    const float* rb = region + (size_t)b * Nn * 5;

    if (t < 256) hist[t] = 0;
    if (t == 0) sh_maxbits = 0u;
    __syncthreads();

    // ---- single pass: score stage + max + histogram ----
    unsigned int lm = 0u;
    for (int j = t; j < Nn; j += BDIM) {
        float sc = __ldg(rb + j * 5 + 4);            // scores > 0
        sscore[j] = sc;
        lm = max(lm, __float_as_uint(sc));
        int bin = min(max((int)(sc * 256.0f), 0), 255);
        atomicAdd(&hist[bin], 1);
    }
#pragma unroll
    for (int off = 16; off; off >>= 1)
        lm = max(lm, __shfl_xor_sync(FULL, lm, off));
    if (lane == 0) atomicMax(&sh_maxbits, lm);
    if (t < MAXD * 5) sneg[t] = neg[(size_t)b * MAXD * 5 + t];
    __syncthreads();

    const bool has_conf = __uint_as_float(sh_maxbits) > CONF;
    const float thresh = has_conf ? CONF : 0.0f;
    const int limit = has_conf ? MAXD : TOPK_;

    // ---- candidate selection with escalation fallback ----
    for (int TARGET = 48;; TARGET <<= 2) {
        if (t < 32) {
            int base = 255 - lane * 8;
            int s = 0;
#pragma unroll
            for (int i = 0; i < 8; i++) s += hist[base - i];
            int pre = s;
#pragma unroll
            for (int off = 1; off < 32; off <<= 1) {
                int v = __shfl_up_sync(FULL, pre, off);
                if (lane >= off) pre += v;
            }
            unsigned bal = __ballot_sync(FULL, pre >= TARGET);
            if (bal) {
                int lw = __ffs(bal) - 1;
                if (lane == lw) {
                    int run = pre - s;
                    int binthr = 0;
#pragma unroll
                    for (int i = 0; i < 8; i++) {
                        run += hist[base - i];
                        if (run >= TARGET) { binthr = base - i; break; }
                    }
                    sh_binthr = binthr;
                }
            } else if (lane == 0) {
                sh_binthr = 0;
            }
            if (lane == 0) { sh_exh = (bal == 0); sh_cnt = 0; sh_found = 0; }
        }
        __syncthreads();
        const int binthr = sh_binthr;

        for (int j = t; j < Nn; j += BDIM) {
            float sc = sscore[j];
            if (sc > thresh) {
                int bin = min(max((int)(sc * 256.0f), 0), 255);
                if (bin >= binthr) {
                    int pos = atomicAdd(&sh_cnt, 1);
                    if (pos < 2048)
                        ckey[pos] = ((unsigned long long)__float_as_uint(sc) << 32) |
                                    (unsigned)(Nn - 1 - j);
                }
            }
        }
        __syncthreads();
        const int C = min(sh_cnt, 2048);

        // rank sort (descending; keys unique -> exact stable order)
        for (int i = t; i < C; i += BDIM) {
            unsigned long long ki = ckey[i];
            int r = 0;
            for (int j = 0; j < C; j++) r += (ckey[j] > ki);
            skeys[r] = ki;
        }
        __syncthreads();

        // ---- single-warp greedy NMS: candidate per lane, suppressor-list check ----
        if (t < 32) {
            int nkept = 0, found = 0;
            for (int c0 = 0; c0 < C; c0 += 32) {
                int ci = c0 + lane;
                bool validl = ci < C;
                float x1 = 0.f, y1 = 0.f, x2 = 0.f, y2 = 0.f, sc = 0.f;
                if (validl) {
                    unsigned long long key = skeys[ci];
                    int js = (Nn - 1) - (int)(unsigned)(key & 0xffffffffu);
                    x1 = __ldg(rb + js * 5 + 0);
                    y1 = __ldg(rb + js * 5 + 1);
                    x2 = __ldg(rb + js * 5 + 2);
                    y2 = __ldg(rb + js * 5 + 3);
                    sc = __uint_as_float((unsigned)(key >> 32));
                }
                bool decided = !validl;
                for (int k = 0; k < nkept; k++) {
                    float4 kb = skept[k];
                    if (!decided && iou_f(kb.x, kb.y, kb.z, kb.w, x1, y1, x2, y2) > IOUT)
                        decided = true;
                }
                bool stop = false;
                for (;;) {
                    unsigned und = __ballot_sync(FULL, !decided);
                    if (!und) break;
                    int i0 = __ffs(und) - 1;
                    float ax1 = __shfl_sync(FULL, x1, i0);
                    float ay1 = __shfl_sync(FULL, y1, i0);
                    float ax2 = __shfl_sync(FULL, x2, i0);
                    float ay2 = __shfl_sync(FULL, y2, i0);
                    if (lane == i0) {
                        skept[nkept] = make_float4(x1, y1, x2, y2);
                        decided = true;
                    }
                    nkept++;
                    bool tiny_ok = (ax2 - ax1 >= 1.0f) && (ay2 - ay1 >= 1.0f);
                    if (tiny_ok) {
                        if (lane == i0) {
                            okx1[found] = x1; oky1[found] = y1;
                            okx2[found] = x2; oky2[found] = y2;
                            oksc[found] = sc;
                        }
                        found++;
                        if (found == limit) { stop = true; break; }
                    }
                    if (!decided &&
                        iou_f(ax1, ay1, ax2, ay2, x1, y1, x2, y2) > IOUT)
                        decided = true;
                    if (nkept == KMAX) { stop = true; break; }
                }
                __syncwarp();
                if (stop) break;
            }
            if (lane == 0) sh_found = found;
        }
        __syncthreads();

        if (sh_found >= limit || sh_exh || TARGET >= Nn) break;
    }

    // ---- stage 2: warp-parallel 10-box merge + stable sort + NMS + outputs ----
    if (t < 32) {
        const int cnt = min(sh_found, limit);
        float bx[5];
        bx[0] = bx[1] = bx[2] = bx[3] = 0.f;
        bx[4] = -1.0f;
        if (lane < MAXD) {
            if (lane < cnt) {
                bx[0] = okx1[lane]; bx[1] = oky1[lane];
                bx[2] = okx2[lane]; bx[3] = oky2[lane];
                bx[4] = oksc[lane];
            } else {
#pragma unroll
                for (int c = 0; c < 5; c++) bx[c] = sneg[lane * 5 + c];
            }
        }
        int rank = 0;
#pragma unroll
        for (int j = 0; j < MAXD; j++) {
            float cj = __shfl_sync(FULL, bx[4], j);
            rank += (cj > bx[4]) || (cj == bx[4] && j < lane);
        }
        if (lane < MAXD) {
#pragma unroll
            for (int c = 0; c < 5; c++) sxb[rank][c] = bx[c];
        }
        __syncwarp();
        if (lane < MAXD) {
#pragma unroll
            for (int c = 0; c < 5; c++) bx[c] = sxb[lane][c];
        }
        bool kp = (lane < MAXD) && (bx[4] > 0.0f);
#pragma unroll
        for (int i = 0; i < MAXD; i++) {
            float ax1 = __shfl_sync(FULL, bx[0], i);
            float ay1 = __shfl_sync(FULL, bx[1], i);
            float ax2 = __shfl_sync(FULL, bx[2], i);
            float ay2 = __shfl_sync(FULL, bx[3], i);
            int ki = __shfl_sync(FULL, (int)kp, i);
            if (ki && lane > i && kp) {
                if (iou_f(ax1, ay1, ax2, ay2, bx[0], bx[1], bx[2], bx[3]) > IOUT)
                    kp = false;
            }
        }
        if (lane < MAXD) {
#pragma unroll
            for (int c = 0; c < 4; c++) {
                out_tb[(size_t)b * MAXD * 4 + lane * 4 + c] = kp ? bx[c] : 0.0f;
                s_ib[lane][c] = (int)floorf(bx[c] + 0.5f);
            }
            out_k2[(size_t)b * MAXD + lane] = kp ? 1.0f : 0.0f;
            s_k[lane] = kp ? 1 : 0;
        }
    }
    __syncthreads();

    // ---- wait for fill completion (acquire), then zero covered pixels ----
    if (t == 0) {
        while (*(volatile int*)&g_fc < FILLB) { }
        __threadfence();
    }
    __syncthreads();

    float* base = out + (size_t)b * Hh * Ww;
#pragma unroll
    for (int k = 0; k < MAXD; k++) {
        if (!s_k[k]) continue;
        int x1 = max(s_ib[k][0], 0), y1 = max(s_ib[k][1], 0);
        int x2 = min(s_ib[k][2], Ww), y2 = min(s_ib[k][3], Hh);
        int w = x2 - x1, h = y2 - y1;
        if (w <= 0 || h <= 0) continue;
        int area = w * h;
        for (int i = t; i < area; i += BDIM) {
            int y = y1 + i / w, x = x1 + i % w;
            base[y * Ww + x] = 0.0f;
        }
    }
    __syncthreads();
    // handshake reset: last NMS block to finish clears the counters for next replay
    if (t == 0) {
        int d = atomicAdd(&g_done, 1);
        if (d == Bn - 1) { g_fc = 0; g_done = 0; }
    }
}

extern "C" void kernel_launch(void* const* d_in, const int* in_sizes, int n_in,
                              void* d_out, int out_size) {
    // inputs: [0]=x (unused), [1]=region_boxes (B,N,5), [2]=neg_boxes (B,10,5)
    const float* region = (const float*)d_in[1];
    const float* neg = (const float*)d_in[2];
    float* out = (float*)d_out;
    float* out_tb = out + (size_t)Bn * Hh * Ww;          // target_boxes segment
    float* out_k2 = out_tb + (size_t)Bn * MAXD * 4;      // keep2 segment

    const int smem_bytes = 45056;
    cudaFuncSetAttribute(fused_kernel, cudaFuncAttributeMaxDynamicSharedMemorySize, smem_bytes);

    fused_kernel<<<GRID, BDIM, smem_bytes>>>(region, neg, out, out_tb, out_k2);
}

// round 10
// speedup vs baseline: 1.1366x; 1.0152x over previous
#include <cuda_runtime.h>
#include <cstdint>
#include <climits>

#define BDIM 512
constexpr int Bn = 16, Nn = 2000, Hh = 512, Ww = 512, MAXD = 10, TOPK_ = 5;
constexpr float CONF = 0.2f, IOUT = 0.4f;
constexpr int KMAX = 256;
constexpr int CCAP = 2048;
constexpr int GRID = 148;                  // one wave: one block per SM
constexpr int FILLB = GRID - Bn;           // 132 fill blocks
constexpr unsigned FULL = 0xffffffffu;

// release/acquire counters (reset by last NMS block each replay)
__device__ int g_fc;
__device__ int g_done;

__device__ __forceinline__ float iou_f(float ax1, float ay1, float ax2, float ay2,
                                       float bx1, float by1, float bx2, float by2) {
    float aA = fmaxf(ax2 - ax1, 0.f) * fmaxf(ay2 - ay1, 0.f);
    float aB = fmaxf(bx2 - bx1, 0.f) * fmaxf(by2 - by1, 0.f);
    float ix1 = fmaxf(ax1, bx1), iy1 = fmaxf(ay1, by1);
    float ix2 = fminf(ax2, bx2), iy2 = fminf(ay2, by2);
    float it = fmaxf(ix2 - ix1, 0.f) * fmaxf(iy2 - iy1, 0.f);
    return it / (aA + aB - it + 1e-9f);
}

extern __shared__ unsigned char dynsmem[];
// NMS-block layout:
//   sscore : float[2048]    @ 0      (8192 B)   raw scores
//   ckey   : ULL[CCAP]      @ 8192   (16384 B)  compacted keys
//   cbox   : float4[CCAP]   @ 24576  (32768 B)  compacted boxes
//   sbox   : float4[CCAP]   @ 57344  (32768 B)  rank-sorted boxes
//   ssc    : float[CCAP]    @ 90112  (8192 B)   rank-sorted scores
// total 98304 B
constexpr int SMEM_TOTAL = 98304;

__global__ __launch_bounds__(BDIM) void fused_kernel(const float* __restrict__ region,
                                                     const float* __restrict__ neg,
                                                     float* __restrict__ out,
                                                     float* __restrict__ out_tb,
                                                     float* __restrict__ out_k2) {
    const int t = threadIdx.x;

    // ---------------- fill blocks: flat stream of 1.0f over whole mask ----------------
    if (blockIdx.x >= Bn) {
        const int fb = blockIdx.x - Bn;
        const int total4 = Bn * Hh * Ww / 4;                 // 1048576 float4
        const int per = (total4 + FILLB - 1) / FILLB;        // 7944
        float4* o4 = (float4*)out;
        float4 one = make_float4(1.f, 1.f, 1.f, 1.f);
        int base = fb * per;
        int end = min(base + per, total4);
        for (int i = base + t; i < end; i += BDIM) o4[i] = one;
        __syncthreads();
        if (t == 0) {
            __threadfence();
            atomicAdd(&g_fc, 1);
        }
        return;
    }

    // ---------------- NMS blocks ----------------
    float* sscore = (float*)dynsmem;
    unsigned long long* ckey = (unsigned long long*)(dynsmem + 8192);
    float4* cbox = (float4*)(dynsmem + 24576);
    float4* sbox = (float4*)(dynsmem + 57344);
    float* ssc = (float*)(dynsmem + 90112);

    __shared__ int hist[256];
    __shared__ float sneg[MAXD * 5];
    __shared__ float okx1[MAXD], oky1[MAXD], okx2[MAXD], oky2[MAXD], oksc[MAXD];
    __shared__ float sxb[MAXD][5];
    __shared__ float4 skept[KMAX];
    __shared__ float sconf0[MAXD];
    __shared__ int s_supb[MAXD];
    __shared__ int s_ib[MAXD][4];
    __shared__ int s_k[MAXD];
    __shared__ unsigned int sh_maxbits;
    __shared__ int sh_binthr, sh_cnt, sh_found, sh_exh;

    const int b = blockIdx.x;
    const int lane = t & 31;
    const float* rb = region + (size_t)b * Nn * 5;

    if (t < 256) hist[t] = 0;
    if (t == 0) sh_maxbits = 0u;
    __syncthreads();

    // ---- single pass: score stage + max + histogram ----
    unsigned int lm = 0u;
    for (int j = t; j < Nn; j += BDIM) {
        float sc = __ldg(rb + j * 5 + 4);            // scores > 0
        sscore[j] = sc;
        lm = max(lm, __float_as_uint(sc));
        int bin = min(max((int)(sc * 256.0f), 0), 255);
        atomicAdd(&hist[bin], 1);
    }
#pragma unroll
    for (int off = 16; off; off >>= 1)
        lm = max(lm, __shfl_xor_sync(FULL, lm, off));
    if (lane == 0) atomicMax(&sh_maxbits, lm);
    if (t < MAXD * 5) sneg[t] = neg[(size_t)b * MAXD * 5 + t];
    __syncthreads();

    const bool has_conf = __uint_as_float(sh_maxbits) > CONF;
    const float thresh = has_conf ? CONF : 0.0f;
    const int limit = has_conf ? MAXD : TOPK_;

    // ---- candidate selection with escalation fallback ----
    for (int TARGET = 48;; TARGET <<= 2) {
        if (t < 32) {
            int base = 255 - lane * 8;
            int s = 0;
#pragma unroll
            for (int i = 0; i < 8; i++) s += hist[base - i];
            int pre = s;
#pragma unroll
            for (int off = 1; off < 32; off <<= 1) {
                int v = __shfl_up_sync(FULL, pre, off);
                if (lane >= off) pre += v;
            }
            unsigned bal = __ballot_sync(FULL, pre >= TARGET);
            if (bal) {
                int lw = __ffs(bal) - 1;
                if (lane == lw) {
                    int run = pre - s;
                    int binthr = 0;
#pragma unroll
                    for (int i = 0; i < 8; i++) {
                        run += hist[base - i];
                        if (run >= TARGET) { binthr = base - i; break; }
                    }
                    sh_binthr = binthr;
                }
            } else if (lane == 0) {
                sh_binthr = 0;
            }
            if (lane == 0) { sh_exh = (bal == 0); sh_cnt = 0; sh_found = 0; }
        }
        __syncthreads();
        const int binthr = sh_binthr;

        // compact keys AND prefetch boxes into shared (parallel scattered loads)
        for (int j = t; j < Nn; j += BDIM) {
            float sc = sscore[j];
            if (sc > thresh) {
                int bin = min(max((int)(sc * 256.0f), 0), 255);
                if (bin >= binthr) {
                    int pos = atomicAdd(&sh_cnt, 1);
                    if (pos < CCAP) {
                        ckey[pos] = ((unsigned long long)__float_as_uint(sc) << 32) |
                                    (unsigned)(Nn - 1 - j);
                        cbox[pos] = make_float4(__ldg(rb + j * 5 + 0),
                                                __ldg(rb + j * 5 + 1),
                                                __ldg(rb + j * 5 + 2),
                                                __ldg(rb + j * 5 + 3));
                    }
                }
            }
        }
        __syncthreads();
        const int C = min(sh_cnt, CCAP);

        // rank sort (descending; keys unique -> exact stable order), permute boxes too
        for (int i = t; i < C; i += BDIM) {
            unsigned long long ki = ckey[i];
            int r = 0;
            for (int j = 0; j < C; j++) r += (ckey[j] > ki);
            sbox[r] = cbox[i];
            ssc[r] = __uint_as_float((unsigned)(ki >> 32));
        }
        __syncthreads();

        // ---- single-warp greedy NMS: candidate per lane, all-shared reads ----
        if (t < 32) {
            int nkept = 0, found = 0;
            for (int c0 = 0; c0 < C; c0 += 32) {
                int ci = c0 + lane;
                bool validl = ci < C;
                float4 bb = validl ? sbox[ci] : make_float4(0.f, 0.f, 0.f, 0.f);
                float sc = validl ? ssc[ci] : 0.f;
                bool decided = !validl;
                for (int k = 0; k < nkept; k++) {
                    float4 kb = skept[k];
                    if (!decided &&
                        iou_f(kb.x, kb.y, kb.z, kb.w, bb.x, bb.y, bb.z, bb.w) > IOUT)
                        decided = true;
                }
                bool stop = false;
                for (;;) {
                    unsigned und = __ballot_sync(FULL, !decided);
                    if (!und) break;
                    int i0 = __ffs(und) - 1;
                    float ax1 = __shfl_sync(FULL, bb.x, i0);
                    float ay1 = __shfl_sync(FULL, bb.y, i0);
                    float ax2 = __shfl_sync(FULL, bb.z, i0);
                    float ay2 = __shfl_sync(FULL, bb.w, i0);
                    if (lane == i0) {
                        skept[nkept] = bb;
                        decided = true;
                    }
                    nkept++;
                    bool tiny_ok = (ax2 - ax1 >= 1.0f) && (ay2 - ay1 >= 1.0f);
                    if (tiny_ok) {
                        if (lane == i0) {
                            okx1[found] = bb.x; oky1[found] = bb.y;
                            okx2[found] = bb.z; oky2[found] = bb.w;
                            oksc[found] = sc;
                        }
                        found++;
                        if (found == limit) { stop = true; break; }
                    }
                    if (!decided &&
                        iou_f(ax1, ay1, ax2, ay2, bb.x, bb.y, bb.z, bb.w) > IOUT)
                        decided = true;
                    if (nkept == KMAX) { stop = true; break; }
                }
                __syncwarp();
                if (stop) break;
            }
            if (lane == 0) sh_found = found;
        }
        __syncthreads();

        if (sh_found >= limit || sh_exh || TARGET >= Nn) break;
    }

    // ---- stage 2: warp-parallel 10-box merge + stable sort + bitmask NMS ----
    if (t < 32) {
        const int cnt = min(sh_found, limit);
        float bx[5];
        bx[0] = bx[1] = bx[2] = bx[3] = 0.f;
        bx[4] = -1.0f;
        if (lane < MAXD) {
            if (lane < cnt) {
                bx[0] = okx1[lane]; bx[1] = oky1[lane];
                bx[2] = okx2[lane]; bx[3] = oky2[lane];
                bx[4] = oksc[lane];
            } else {
#pragma unroll
                for (int c = 0; c < 5; c++) bx[c] = sneg[lane * 5 + c];
            }
            sconf0[lane] = bx[4];
        }
        __syncwarp();
        // stable descending rank by conf (ties -> original slot order), via shared
        if (lane < MAXD) {
            int rank = 0;
#pragma unroll
            for (int j = 0; j < MAXD; j++) {
                float cj = sconf0[j];
                rank += (cj > bx[4]) || (cj == bx[4] && j < lane);
            }
#pragma unroll
            for (int c = 0; c < 5; c++) sxb[rank][c] = bx[c];
        }
        __syncwarp();
        if (lane < MAXD) {
#pragma unroll
            for (int c = 0; c < 5; c++) bx[c] = sxb[lane][c];
        }
        __syncwarp();
        // per-lane suppression bitmask vs every box (parallel IOU matrix)
        unsigned supb = 0;
        if (lane < MAXD) {
#pragma unroll
            for (int j = 0; j < MAXD; j++) {
                if (iou_f(sxb[j][0], sxb[j][1], sxb[j][2], sxb[j][3],
                          bx[0], bx[1], bx[2], bx[3]) > IOUT)
                    supb |= (1u << j);
            }
            s_supb[lane] = (int)supb;
        }
        unsigned validm = __ballot_sync(FULL, lane < MAXD && bx[4] > 0.0f);
        __syncwarp();
        // sequential keep recurrence, pure ALU, identical on all lanes
        unsigned kept = 0;
#pragma unroll
        for (int i = 0; i < MAXD; i++) {
            if ((validm >> i) & 1u) {
                if (((unsigned)s_supb[i] & kept & ((1u << i) - 1u)) == 0u)
                    kept |= (1u << i);
            }
        }
        bool kp = (lane < MAXD) && ((kept >> lane) & 1u);
        if (lane < MAXD) {
#pragma unroll
            for (int c = 0; c < 4; c++) {
                out_tb[(size_t)b * MAXD * 4 + lane * 4 + c] = kp ? bx[c] : 0.0f;
                s_ib[lane][c] = (int)floorf(bx[c] + 0.5f);
            }
            out_k2[(size_t)b * MAXD + lane] = kp ? 1.0f : 0.0f;
            s_k[lane] = kp ? 1 : 0;
        }
    }
    __syncthreads();

    // ---- wait for fill completion (acquire), then zero covered pixels ----
    if (t == 0) {
        while (*(volatile int*)&g_fc < FILLB) { }
        __threadfence();
    }
    __syncthreads();

    float* base = out + (size_t)b * Hh * Ww;
#pragma unroll
    for (int k = 0; k < MAXD; k++) {
        if (!s_k[k]) continue;
        int x1 = max(s_ib[k][0], 0), y1 = max(s_ib[k][1], 0);
        int x2 = min(s_ib[k][2], Ww), y2 = min(s_ib[k][3], Hh);
        int w = x2 - x1, h = y2 - y1;
        if (w <= 0 || h <= 0) continue;
        int area = w * h;
        for (int i = t; i < area; i += BDIM) {
            int y = y1 + i / w, x = x1 + i % w;
            base[y * Ww + x] = 0.0f;
        }
    }
    __syncthreads();
    // handshake reset: last NMS block clears counters for next graph replay
    if (t == 0) {
        int d = atomicAdd(&g_done, 1);
        if (d == Bn - 1) { g_fc = 0; g_done = 0; }
    }
}

extern "C" void kernel_launch(void* const* d_in, const int* in_sizes, int n_in,
                              void* d_out, int out_size) {
    // inputs: [0]=x (unused), [1]=region_boxes (B,N,5), [2]=neg_boxes (B,10,5)
    const float* region = (const float*)d_in[1];
    const float* neg = (const float*)d_in[2];
    float* out = (float*)d_out;
    float* out_tb = out + (size_t)Bn * Hh * Ww;          // target_boxes segment
    float* out_k2 = out_tb + (size_t)Bn * MAXD * 4;      // keep2 segment

    cudaFuncSetAttribute(fused_kernel, cudaFuncAttributeMaxDynamicSharedMemorySize, SMEM_TOTAL);
    fused_kernel<<<GRID, BDIM, SMEM_TOTAL>>>(region, neg, out, out_tb, out_k2);
}

// round 11
// speedup vs baseline: 1.2965x; 1.1407x over previous
#include <cuda_runtime.h>
#include <cstdint>
#include <climits>

#define BDIM 512
constexpr int Bn = 16, Nn = 2000, Hh = 512, Ww = 512, MAXD = 10, TOPK_ = 5;
constexpr float CONF = 0.2f, IOUT = 0.4f;
constexpr int KMAX = 256;
constexpr int CCAP = 2048;
constexpr int GRID = 148;                  // one wave: one block per SM
constexpr int FILLB = GRID - Bn;           // 132 fill blocks
constexpr unsigned FULL = 0xffffffffu;

// release/acquire counters (reset by last NMS block each replay)
__device__ int g_fc;
__device__ int g_done;

// IOU > IOUT  <=>  inter*(1+IOUT) > IOUT*(areaA+areaB+1e-9)   (denominator > 0)
__device__ __forceinline__ bool iou_gt(float ax1, float ay1, float ax2, float ay2, float aA,
                                       float bx1, float by1, float bx2, float by2, float aB) {
    float ix1 = fmaxf(ax1, bx1), iy1 = fmaxf(ay1, by1);
    float ix2 = fminf(ax2, bx2), iy2 = fminf(ay2, by2);
    float it = fmaxf(ix2 - ix1, 0.f) * fmaxf(iy2 - iy1, 0.f);
    return it * (1.0f + IOUT) > IOUT * (aA + aB + 1e-9f);
}

extern __shared__ unsigned char dynsmem[];
// layout:
//   sdata : float[10240]   @ 0       (40960 B; region slice)
//   ckey  : ULL[CCAP]      @ 40960   (16384 B)
//   sbox  : float4[CCAP]   @ 57344   (32768 B)  sorted boxes
//   ssc   : float[CCAP]    @ 90112   (8192 B)   sorted scores
//   sarea : float[CCAP]    @ 98304   (8192 B)   sorted areas
// total 106496 B
constexpr int SMEM_TOTAL = 106496;

__global__ __launch_bounds__(BDIM) void fused_kernel(const float* __restrict__ region,
                                                     const float* __restrict__ neg,
                                                     float* __restrict__ out,
                                                     float* __restrict__ out_tb,
                                                     float* __restrict__ out_k2) {
    const int t = threadIdx.x;

    // ---------------- fill blocks: flat stream of 1.0f over whole mask ----------------
    if (blockIdx.x >= Bn) {
        const int fb = blockIdx.x - Bn;
        const int total4 = Bn * Hh * Ww / 4;
        const int per = (total4 + FILLB - 1) / FILLB;
        float4* o4 = (float4*)out;
        float4 one = make_float4(1.f, 1.f, 1.f, 1.f);
        int base = fb * per;
        int end = min(base + per, total4);
        for (int i = base + t; i < end; i += BDIM) o4[i] = one;
        __syncthreads();
        if (t == 0) {
            __threadfence();
            atomicAdd(&g_fc, 1);
        }
        return;
    }

    // ---------------- NMS blocks ----------------
    float* sdata = (float*)dynsmem;
    unsigned long long* ckey = (unsigned long long*)(dynsmem + 40960);
    float4* sbox = (float4*)(dynsmem + 57344);
    float* ssc = (float*)(dynsmem + 90112);
    float* sarea = (float*)(dynsmem + 98304);

    __shared__ int hist[256];
    __shared__ float sneg[MAXD * 5];
    __shared__ float okx1[MAXD], oky1[MAXD], okx2[MAXD], oky2[MAXD], oksc[MAXD];
    __shared__ float sxb[MAXD][5];
    __shared__ float4 skept[KMAX];
    __shared__ float skarea[KMAX];
    __shared__ unsigned s_sup[32];
    __shared__ float sconf0[MAXD];
    __shared__ int s_supb[MAXD];
    __shared__ int s_ib[MAXD][4];
    __shared__ int s_k[MAXD];
    __shared__ unsigned int sh_maxbits;
    __shared__ int sh_binthr, sh_cnt, sh_found, sh_exh;

    const int b = blockIdx.x;
    const int lane = t & 31;
    const float* rb = region + (size_t)b * Nn * 5;

    if (t < 256) hist[t] = 0;
    if (t == 0) sh_maxbits = 0u;

    // ---- coalesced stage of the whole region slice (2500 float4) + neg ----
    {
        const float4* rb4 = (const float4*)rb;
        float4* s4 = (float4*)sdata;
        for (int i = t; i < Nn * 5 / 4; i += BDIM) s4[i] = rb4[i];
        if (t < MAXD * 5) sneg[t] = neg[(size_t)b * MAXD * 5 + t];
    }
    __syncthreads();

    // ---- score pass from smem: max + histogram (stride-5 LDS: conflict-free) ----
    unsigned int lm = 0u;
    for (int j = t; j < Nn; j += BDIM) {
        float sc = sdata[j * 5 + 4];                 // scores > 0
        lm = max(lm, __float_as_uint(sc));
        int bin = min(max((int)(sc * 256.0f), 0), 255);
        atomicAdd(&hist[bin], 1);
    }
#pragma unroll
    for (int off = 16; off; off >>= 1)
        lm = max(lm, __shfl_xor_sync(FULL, lm, off));
    if (lane == 0) atomicMax(&sh_maxbits, lm);
    __syncthreads();

    const bool has_conf = __uint_as_float(sh_maxbits) > CONF;
    const float thresh = has_conf ? CONF : 0.0f;
    const int limit = has_conf ? MAXD : TOPK_;

    // ---- candidate selection with escalation fallback ----
    for (int TARGET = 48;; TARGET <<= 2) {
        if (t < 32) {
            int base = 255 - lane * 8;
            int s = 0;
#pragma unroll
            for (int i = 0; i < 8; i++) s += hist[base - i];
            int pre = s;
#pragma unroll
            for (int off = 1; off < 32; off <<= 1) {
                int v = __shfl_up_sync(FULL, pre, off);
                if (lane >= off) pre += v;
            }
            unsigned bal = __ballot_sync(FULL, pre >= TARGET);
            if (bal) {
                int lw = __ffs(bal) - 1;
                if (lane == lw) {
                    int run = pre - s;
                    int binthr = 0;
#pragma unroll
                    for (int i = 0; i < 8; i++) {
                        run += hist[base - i];
                        if (run >= TARGET) { binthr = base - i; break; }
                    }
                    sh_binthr = binthr;
                }
            } else if (lane == 0) {
                sh_binthr = 0;
            }
            if (lane == 0) { sh_exh = (bal == 0); sh_cnt = 0; sh_found = 0; }
        }
        __syncthreads();
        const int binthr = sh_binthr;

        // compact keys (boxes stay in sdata; key low bits recover index)
        for (int j = t; j < Nn; j += BDIM) {
            float sc = sdata[j * 5 + 4];
            if (sc > thresh) {
                int bin = min(max((int)(sc * 256.0f), 0), 255);
                if (bin >= binthr) {
                    int pos = atomicAdd(&sh_cnt, 1);
                    if (pos < CCAP)
                        ckey[pos] = ((unsigned long long)__float_as_uint(sc) << 32) |
                                    (unsigned)(Nn - 1 - j);
                }
            }
        }
        __syncthreads();
        const int C = min(sh_cnt, CCAP);

        // rank sort -> sorted boxes/scores/areas directly
        for (int i = t; i < C; i += BDIM) {
            unsigned long long ki = ckey[i];
            int r = 0;
            for (int j = 0; j < C; j++) r += (ckey[j] > ki);
            int js = (Nn - 1) - (int)(unsigned)(ki & 0xffffffffu);
            float x1 = sdata[js * 5 + 0], y1 = sdata[js * 5 + 1];
            float x2 = sdata[js * 5 + 2], y2 = sdata[js * 5 + 3];
            sbox[r] = make_float4(x1, y1, x2, y2);
            sarea[r] = fmaxf(x2 - x1, 0.f) * fmaxf(y2 - y1, 0.f);
            ssc[r] = __uint_as_float((unsigned)(ki >> 32));
        }
        __syncthreads();

        // ---- single-warp greedy NMS: parallel IOU matrix + ALU recurrence ----
        if (t < 32) {
            int nkept = 0, found = 0;
            bool stop = false;
            for (int c0 = 0; c0 < C && !stop; c0 += 32) {
                int ci = c0 + lane;
                bool valid = ci < C;
                float4 bb = valid ? sbox[ci] : make_float4(0.f, 0.f, 0.f, 0.f);
                float ar = valid ? sarea[ci] : 0.f;
                float sc = valid ? ssc[ci] : 0.f;
                // pre-kill vs suppressors from earlier chunks (broadcast LDS)
                bool alive = valid;
                for (int k = 0; k < nkept; k++) {
                    float4 kb = skept[k];
                    if (alive && iou_gt(kb.x, kb.y, kb.z, kb.w, skarea[k],
                                        bb.x, bb.y, bb.z, bb.w, ar))
                        alive = false;
                }
                // in-chunk suppression mask: bit j (j < lane) if j would suppress me
                unsigned sup = 0;
#pragma unroll 4
                for (int j = 0; j < 32; j++) {
                    if (j < lane && valid) {
                        float4 jb = sbox[c0 + j];
                        if (iou_gt(jb.x, jb.y, jb.z, jb.w, sarea[c0 + j],
                                   bb.x, bb.y, bb.z, bb.w, ar))
                            sup |= (1u << j);
                    }
                }
                s_sup[lane] = sup;
                unsigned alivem = __ballot_sync(FULL, alive);
                bool tiny = valid && (bb.z - bb.x >= 1.0f) && (bb.w - bb.y >= 1.0f);
                unsigned tinym = __ballot_sync(FULL, tiny);
                __syncwarp();
                // greedy keep recurrence, pure ALU, identical on all lanes
                unsigned kept = 0;
#pragma unroll 4
                for (int i = 0; i < 32; i++) {
                    if ((alivem >> i) & 1u) {
                        if ((s_sup[i] & kept) == 0u) kept |= (1u << i);
                    }
                }
                unsigned ktiny = kept & tinym;
                int cf = __popc(ktiny);
                if ((ktiny >> lane) & 1u) {
                    int r = found + __popc(ktiny & ((1u << lane) - 1u));
                    if (r < limit) {
                        okx1[r] = bb.x; oky1[r] = bb.y;
                        okx2[r] = bb.z; oky2[r] = bb.w;
                        oksc[r] = sc;
                    }
                }
                if (found + cf >= limit) {
                    found = limit;
                    stop = true;
                } else {
                    found += cf;
                    if ((kept >> lane) & 1u) {
                        int p = nkept + __popc(kept & ((1u << lane) - 1u));
                        if (p < KMAX) { skept[p] = bb; skarea[p] = ar; }
                    }
                    nkept += __popc(kept);
                    if (nkept >= KMAX) stop = true;
                }
                __syncwarp();
            }
            if (lane == 0) sh_found = found;
        }
        __syncthreads();

        if (sh_found >= limit || sh_exh || TARGET >= Nn) break;
    }

    // ---- stage 2: warp-parallel 10-box merge + stable sort + bitmask NMS ----
    if (t < 32) {
        const int cnt = min(sh_found, limit);
        float bx[5];
        bx[0] = bx[1] = bx[2] = bx[3] = 0.f;
        bx[4] = -1.0f;
        if (lane < MAXD) {
            if (lane < cnt) {
                bx[0] = okx1[lane]; bx[1] = oky1[lane];
                bx[2] = okx2[lane]; bx[3] = oky2[lane];
                bx[4] = oksc[lane];
            } else {
#pragma unroll
                for (int c = 0; c < 5; c++) bx[c] = sneg[lane * 5 + c];
            }
            sconf0[lane] = bx[4];
        }
        __syncwarp();
        if (lane < MAXD) {
            int rank = 0;
#pragma unroll
            for (int j = 0; j < MAXD; j++) {
                float cj = sconf0[j];
                rank += (cj > bx[4]) || (cj == bx[4] && j < lane);
            }
#pragma unroll
            for (int c = 0; c < 5; c++) sxb[rank][c] = bx[c];
        }
        __syncwarp();
        if (lane < MAXD) {
#pragma unroll
            for (int c = 0; c < 5; c++) bx[c] = sxb[lane][c];
        }
        __syncwarp();
        unsigned supb = 0;
        if (lane < MAXD) {
            float aA = fmaxf(bx[2] - bx[0], 0.f) * fmaxf(bx[3] - bx[1], 0.f);
#pragma unroll
            for (int j = 0; j < MAXD; j++) {
                float jx1 = sxb[j][0], jy1 = sxb[j][1], jx2 = sxb[j][2], jy2 = sxb[j][3];
                float aJ = fmaxf(jx2 - jx1, 0.f) * fmaxf(jy2 - jy1, 0.f);
                if (iou_gt(jx1, jy1, jx2, jy2, aJ, bx[0], bx[1], bx[2], bx[3], aA))
                    supb |= (1u << j);
            }
            s_supb[lane] = (int)supb;
        }
        unsigned validm = __ballot_sync(FULL, lane < MAXD && bx[4] > 0.0f);
        __syncwarp();
        unsigned kept = 0;
#pragma unroll
        for (int i = 0; i < MAXD; i++) {
            if ((validm >> i) & 1u) {
                if (((unsigned)s_supb[i] & kept & ((1u << i) - 1u)) == 0u)
                    kept |= (1u << i);
            }
        }
        bool kp = (lane < MAXD) && ((kept >> lane) & 1u);
        if (lane < MAXD) {
#pragma unroll
            for (int c = 0; c < 4; c++) {
                out_tb[(size_t)b * MAXD * 4 + lane * 4 + c] = kp ? bx[c] : 0.0f;
                s_ib[lane][c] = (int)floorf(bx[c] + 0.5f);
            }
            out_k2[(size_t)b * MAXD + lane] = kp ? 1.0f : 0.0f;
            s_k[lane] = kp ? 1 : 0;
        }
    }
    __syncthreads();

    // ---- wait for fill completion (acquire), then zero covered pixels ----
    if (t == 0) {
        while (*(volatile int*)&g_fc < FILLB) { }
        __threadfence();
    }
    __syncthreads();

    float* base = out + (size_t)b * Hh * Ww;
#pragma unroll
    for (int k = 0; k < MAXD; k++) {
        if (!s_k[k]) continue;
        int x1 = max(s_ib[k][0], 0), y1 = max(s_ib[k][1], 0);
        int x2 = min(s_ib[k][2], Ww), y2 = min(s_ib[k][3], Hh);
        int w = x2 - x1, h = y2 - y1;
        if (w <= 0 || h <= 0) continue;
        int area = w * h;
        for (int i = t; i < area; i += BDIM) {
            int y = y1 + i / w, x = x1 + i % w;
            base[y * Ww + x] = 0.0f;
        }
    }
    __syncthreads();
    if (t == 0) {
        int d = atomicAdd(&g_done, 1);
        if (d == Bn - 1) { g_fc = 0; g_done = 0; }
    }
}

extern "C" void kernel_launch(void* const* d_in, const int* in_sizes, int n_in,
                              void* d_out, int out_size) {
    // inputs: [0]=x (unused), [1]=region_boxes (B,N,5), [2]=neg_boxes (B,10,5)
    const float* region = (const float*)d_in[1];
    const float* neg = (const float*)d_in[2];
    float* out = (float*)d_out;
    float* out_tb = out + (size_t)Bn * Hh * Ww;          // target_boxes segment
    float* out_k2 = out_tb + (size_t)Bn * MAXD * 4;      // keep2 segment

    cudaFuncSetAttribute(fused_kernel, cudaFuncAttributeMaxDynamicSharedMemorySize, SMEM_TOTAL);
    fused_kernel<<<GRID, BDIM, SMEM_TOTAL>>>(region, neg, out, out_tb, out_k2);
}